// round 16
// baseline (speedup 1.0000x reference)
#include <cuda_runtime.h>

// Quanv layer, circuit collapsed to per-qubit Bloch components + Pauli strings:
//   out_q = cos(p_{3+q}) * <Z_q>_w  -  sin(p_{3+q}) * <X_q>_w
// Best-measured configuration (R8): single flat kernel, 512-thread CTAs,
// launch_bounds(512,4) -> 32 regs, 2 patches/thread front-batched (MLP=2),
// MUFU trig (abs err ~5e-7, tol 1e-3). This round: param loads vectorized
// (3 LDG instead of 7) to shrink the prologue; loads stay ahead of it.

__device__ __forceinline__ float4 quanv_one(
    float4 a, float Cp0, float p1, float Cp2,
    float4 C, float4 S)
{
    const float PI = 3.14159265358979323846f;

    // Per-qubit Bloch (x, z) after encoding RY(pi*a_q) + layer-1 gate.
    float t0 = a.x * PI;
    float x0 = __sinf(t0);              // RX leaves X
    float z0 = Cp0 * __cosf(t0);        // RX: z' = cos(p0) * z   (y = 0)

    float t1 = fmaf(a.y, PI, p1);       // RY(p1) adds angles
    float x1 = __sinf(t1);
    float z1 = __cosf(t1);

    float t2 = a.z * PI;
    float x2 = Cp2 * __sinf(t2);        // RZ: x' = cos(p2) * x
    float z2 = __cosf(t2);              // RZ leaves Z

    float t3 = a.w * PI;
    float x3 = __cosf(t3);              // H swaps X <-> Z
    float z3 = __sinf(t3);

    // Pauli strings after conjugating Z_q / X_q through the CNOT ring.
    float z01 = z0 * z1;
    float z23 = z2 * z3;
    float Z0w = z1 * z23;               // Z1 Z2 Z3
    float Z1w = z01;                    // Z0 Z1
    float Z2w = z01 * z2;               // Z0 Z1 Z2
    float Z3w = z01 * z23;              // Z0 Z1 Z2 Z3

    float x01 = x0 * x1;
    float X0w = x01;                    // X0 X1
    float X1w = x1 * x2;                // X1 X2
    float X2w = x2 * x3;                // X2 X3
    float X3w = x01 * x3;               // X0 X1 X3

    float4 o;
    o.x = fmaf(C.x, Z0w, -S.x * X0w);
    o.y = fmaf(C.y, Z1w, -S.y * X1w);
    o.z = fmaf(C.z, Z2w, -S.z * X2w);
    o.w = fmaf(C.w, Z3w, -S.w * X3w);
    return o;
}

__global__ __launch_bounds__(512, 4) void quanv_kernel(
    const float* __restrict__ x,      // [n, 4] angles
    const float* __restrict__ params, // [7]
    float* __restrict__ out,          // [n, 4]
    int n)
{
    int half = n >> 1;
    int idx = blockIdx.x * blockDim.x + threadIdx.x;

    const float4* xin = (const float4*)x;
    float4* xout = (float4*)out;

    // Front-batch the two patch loads (independent -> MLP=2, in flight
    // while the param prologue computes).
    float4 a0, a1;
    bool main_lane = (idx < half);
    if (main_lane) {
        a0 = xin[idx];
        a1 = xin[idx + half];
    }

    // Params via 3 vector loads (broadcast, L2-resident after warmup).
    float4 pA = __ldg((const float4*)params);          // p0..p3
    float2 pB = __ldg((const float2*)(params + 4));    // p4, p5
    float  p6 = __ldg(params + 6);

    float Cp0 = __cosf(pA.x);
    float p1  = pA.y;
    float Cp2 = __cosf(pA.z);
    float4 C, S;
    C.x = __cosf(pA.w); S.x = __sinf(pA.w);
    C.y = __cosf(pB.x); S.y = __sinf(pB.x);
    C.z = __cosf(pB.y); S.z = __sinf(pB.y);
    C.w = __cosf(p6);   S.w = __sinf(p6);

    if (main_lane) {
        xout[idx]        = quanv_one(a0, Cp0, p1, Cp2, C, S);
        xout[idx + half] = quanv_one(a1, Cp0, p1, Cp2, C, S);
    }

    // Tail for odd n (not hit for this problem's shapes).
    if (idx == 0 && (n & 1)) {
        xout[n - 1] = quanv_one(xin[n - 1], Cp0, p1, Cp2, C, S);
    }
}

extern "C" void kernel_launch(void* const* d_in, const int* in_sizes, int n_in,
                              void* d_out, int out_size)
{
    const float* x      = (const float*)d_in[0];   // [2048,3,196,4] fp32
    const float* params = (const float*)d_in[1];   // [7] fp32
    float* out = (float*)d_out;                    // flat [n,4] fp32

    int n = in_sizes[0] / 4;       // patches
    int half = n >> 1;
    int threads = 512;
    int blocks = (half + threads - 1) / threads;
    if (blocks < 1) blocks = 1;
    quanv_kernel<<<blocks, threads>>>(x, params, out, n);
}